// round 16
// baseline (speedup 1.0000x reference)
#include <cuda_runtime.h>
#include <cuda_fp16.h>
#include <math.h>
#include <stdint.h>

// Problem constants
#define H_HEADS 25
#define B_DIM   8
#define N_TOK   1025
#define C_DIM   3200
#define D_HEAD  128
#define M_ROWS  (B_DIM * N_TOK)   // 8200

// Scratch (device globals)
__device__ __half g_qkvh[(size_t)M_ROWS * 3 * C_DIM];     // fp16 qkv (normed in place)
__device__ __half g_xh[(size_t)M_ROWS * C_DIM];           // x in fp16
__device__ __half g_wqkvh[(size_t)C_DIM * 3 * C_DIM];     // qkv_w in fp16
__device__ __half g_wprojh[(size_t)C_DIM * C_DIM];        // proj_w in fp16
__device__ __half g_atth[(size_t)M_ROWS * C_DIM];         // attention out in fp16

__device__ __forceinline__ void cp16(uint32_t dst, const void* src, int bytes) {
    asm volatile("cp.async.cg.shared.global [%0], [%1], 16, %2;\n"
                 :: "r"(dst), "l"(src), "r"(bytes));
}
__device__ __forceinline__ void cp16u(uint32_t dst, const void* src) {
    asm volatile("cp.async.cg.shared.global [%0], [%1], 16;\n"
                 :: "r"(dst), "l"(src));
}
__device__ __forceinline__ void cp_commit() { asm volatile("cp.async.commit_group;\n" ::); }
template<int NN>
__device__ __forceinline__ void cp_wait() { asm volatile("cp.async.wait_group %0;\n" :: "n"(NN)); }

__device__ __forceinline__ uint32_t smem_u32(const void* p) {
    return (uint32_t)__cvta_generic_to_shared(p);
}

__device__ __forceinline__ void mma_f16(float (&d)[4], const unsigned (&a)[4], const unsigned (&b)[2]) {
    asm volatile(
        "mma.sync.aligned.m16n8k16.row.col.f32.f16.f16.f32 "
        "{%0,%1,%2,%3}, {%4,%5,%6,%7}, {%8,%9}, {%0,%1,%2,%3};"
        : "+f"(d[0]), "+f"(d[1]), "+f"(d[2]), "+f"(d[3])
        : "r"(a[0]), "r"(a[1]), "r"(a[2]), "r"(a[3]), "r"(b[0]), "r"(b[1]));
}

__device__ __forceinline__ unsigned pack_h2(float a, float b) {
    __half2 h = __floats2half2_rn(a, b);
    return *reinterpret_cast<unsigned*>(&h);
}

#define LDSM_X4(r0, r1, r2, r3, addr) \
    asm volatile("ldmatrix.sync.aligned.m8n8.x4.shared.b16 {%0,%1,%2,%3}, [%4];" \
                 : "=r"(r0), "=r"(r1), "=r"(r2), "=r"(r3) : "r"(addr))
#define LDSM_X4_T(r0, r1, r2, r3, addr) \
    asm volatile("ldmatrix.sync.aligned.m8n8.x4.trans.shared.b16 {%0,%1,%2,%3}, [%4];" \
                 : "=r"(r0), "=r"(r1), "=r"(r2), "=r"(r3) : "r"(addr))

// =====================================================================
// FP16 GEMM (validated R15): 128x128x64 tile, 2 CTAs/SM, 3-stage pipe,
// double-buffered ldmatrix fragments. Requires N % 128 == 0, K % 64 == 0.
// =====================================================================
#define HG_AB   (128 * 72 * 2)               // 18432 B
#define HG_BB   (64 * 136 * 2)               // 17408 B
#define HG_STB  (HG_AB + HG_BB)              // 35840 B
#define HG_SMEM (3 * HG_STB)                 // 107520 B

template<typename OutT>
__global__ void __launch_bounds__(256, 2)
hgemm(const __half* __restrict__ A, const __half* __restrict__ B,
      const float* __restrict__ bias, OutT* __restrict__ C,
      int M, int N, int K, long lda, long ldb, long ldc, int TM, int TN)
{
    extern __shared__ __half hsm[];

    int tm, tn;
    {
        const int GM = 16;
        int per = GM * TN;
        int g = blockIdx.x / per, r = blockIdx.x - g * per;
        int rows = TM - g * GM; if (rows > GM) rows = GM;
        tm = g * GM + r % rows;
        tn = r / rows;
    }
    const int bm0 = tm * 128;
    const int bn0 = tn * 128;

    const int tid = threadIdx.x;
    const int lane = tid & 31, warp = tid >> 5;
    const int wm = warp & 1, wn = warp >> 1;
    const int lr = lane >> 2, lc = lane & 3;

    const uint32_t smbase = smem_u32(hsm);
    const int j8 = lane >> 3, i8 = lane & 7;
    const uint32_t a_lane = (uint32_t)((wm * 64 + (j8 & 1) * 8 + i8) * 144 + (j8 >> 1) * 16);
    const uint32_t b_lane = (uint32_t)(((j8 & 1) * 8 + i8) * 272 + (wn * 32 + (j8 >> 1) * 8) * 2);

    const int arow0 = tid >> 3;
    const int ac = tid & 7;
    const __half* aP = A + (size_t)(bm0 + arow0) * lda + ac * 8;
    const uint32_t adst0 = (uint32_t)(arow0 * 144 + ac * 16);
    int abytes[4];
    #pragma unroll
    for (int i = 0; i < 4; i++)
        abytes[i] = (bm0 + arow0 + 32 * i < M) ? 16 : 0;
    const size_t alda32 = (size_t)32 * lda;
    const int bkr0 = tid >> 4;
    const int bnc = tid & 15;
    const __half* bP = B + (size_t)bkr0 * ldb + bn0 + bnc * 8;
    const uint32_t bdst0 = (uint32_t)(bkr0 * 272 + bnc * 16);
    const size_t bldb16 = (size_t)16 * ldb;
    const size_t bstep = (size_t)64 * ldb;

    float acc[4][4][4];
    #pragma unroll
    for (int mi = 0; mi < 4; mi++)
        #pragma unroll
        for (int ni = 0; ni < 4; ni++)
            #pragma unroll
            for (int r = 0; r < 4; r++)
                acc[mi][ni][r] = 0.f;

    const int T = K / 64;

    auto load_tiles = [&](int t, int s) {
        uint32_t sb = smbase + (uint32_t)s * HG_STB;
        const __half* ap = aP + (size_t)t * 64;
        #pragma unroll
        for (int i = 0; i < 4; i++)
            cp16(sb + adst0 + (uint32_t)(i * 32 * 144), ap + (size_t)i * alda32, abytes[i]);
        uint32_t sbb = sb + HG_AB;
        const __half* bp = bP + (size_t)t * bstep;
        #pragma unroll
        for (int i = 0; i < 4; i++)
            cp16u(sbb + bdst0 + (uint32_t)(i * 16 * 272), bp + (size_t)i * bldb16);
    };

    load_tiles(0, 0); cp_commit();
    if (T > 1) load_tiles(1, 1);
    cp_commit();

    unsigned af[2][4][4], bf[2][2][4];
    int scur = 0, snext = 2;
    for (int t = 0; t < T; t++) {
        if (t + 1 < T) cp_wait<1>(); else cp_wait<0>();
        __syncthreads();
        if (t + 2 < T) { load_tiles(t + 2, snext); }
        cp_commit();
        uint32_t abase = smbase + (uint32_t)scur * HG_STB + a_lane;
        uint32_t bbase = smbase + (uint32_t)scur * HG_STB + HG_AB + b_lane;
        if (++scur == 3) scur = 0;
        if (++snext == 3) snext = 0;

        #pragma unroll
        for (int mi = 0; mi < 4; mi++)
            LDSM_X4(af[0][mi][0], af[0][mi][1], af[0][mi][2], af[0][mi][3],
                    abase + (uint32_t)(mi * 2304));
        #pragma unroll
        for (int nb = 0; nb < 2; nb++)
            LDSM_X4_T(bf[0][nb][0], bf[0][nb][1], bf[0][nb][2], bf[0][nb][3],
                      bbase + (uint32_t)(nb * 32));

        #pragma unroll
        for (int ks = 0; ks < 4; ks++) {
            int cur = ks & 1, nxt = cur ^ 1;
            if (ks < 3) {
                #pragma unroll
                for (int mi = 0; mi < 4; mi++)
                    LDSM_X4(af[nxt][mi][0], af[nxt][mi][1], af[nxt][mi][2], af[nxt][mi][3],
                            abase + (uint32_t)(mi * 2304 + (ks + 1) * 32));
                #pragma unroll
                for (int nb = 0; nb < 2; nb++)
                    LDSM_X4_T(bf[nxt][nb][0], bf[nxt][nb][1], bf[nxt][nb][2], bf[nxt][nb][3],
                              bbase + (uint32_t)(nb * 32 + (ks + 1) * 4352));
            }
            #pragma unroll
            for (int mi = 0; mi < 4; mi++)
                #pragma unroll
                for (int nb = 0; nb < 2; nb++) {
                    unsigned b0[2] = { bf[cur][nb][0], bf[cur][nb][1] };
                    unsigned b1[2] = { bf[cur][nb][2], bf[cur][nb][3] };
                    mma_f16(acc[mi][nb * 2],     af[cur][mi], b0);
                    mma_f16(acc[mi][nb * 2 + 1], af[cur][mi], b1);
                }
        }
    }

    #pragma unroll
    for (int mi = 0; mi < 4; mi++) {
        #pragma unroll
        for (int ni = 0; ni < 4; ni++) {
            int r0 = bm0 + wm * 64 + mi * 16 + lr;
            int c0 = bn0 + wn * 32 + ni * 8 + lc * 2;
            float b0 = 0.f, b1 = 0.f;
            if (bias) { b0 = bias[c0]; b1 = bias[c0 + 1]; }
            #pragma unroll
            for (int rr = 0; rr < 2; rr++) {
                int rw = r0 + rr * 8;
                if (rw < M) {
                    float v0 = acc[mi][ni][rr * 2]     + b0;
                    float v1 = acc[mi][ni][rr * 2 + 1] + b1;
                    if constexpr (sizeof(OutT) == 2) {
                        *reinterpret_cast<__half2*>(
                            reinterpret_cast<__half*>(C) + (size_t)rw * ldc + c0) =
                            __floats2half2_rn(v0, v1);
                    } else {
                        reinterpret_cast<float*>(C)[(size_t)rw * ldc + c0]     = v0;
                        reinterpret_cast<float*>(C)[(size_t)rw * ldc + c0 + 1] = v1;
                    }
                }
            }
        }
    }
}

// =====================================================================
// Fused flash attention, fp16, KV tile 128 (9 tiles instead of 17).
// Warp grid 4 (q-groups of 32) x 2 (kv halves of 64).
// smem: Q[128][136]h + 2 stages of (K[128][136]h, V[128][136]h).
// =====================================================================
#define FAH_QB   (128 * 136 * 2)             // 34816 B
#define FAH_KVB  (128 * 136 * 2)             // 34816 B per K or V
#define FAH_SMEM (FAH_QB + 4 * FAH_KVB + 1024)   // 175104 B
#define FA_T     9                            // ceil(1025/128)

__global__ void __launch_bounds__(256, 1)
flash_attn_h(const __half* __restrict__ qkvh, __half* __restrict__ Og)
{
    extern __shared__ char fsm[];
    const uint32_t smb = smem_u32(fsm);
    const int tid = threadIdx.x, w = tid >> 5, lane = tid & 31;
    const int wr = w >> 1, wc = w & 1;
    const int lr = lane >> 2, lc = lane & 3;
    const int j8 = lane >> 3, i8 = lane & 7;
    const int qt = blockIdx.x, bh = blockIdx.y;
    const int b = bh / H_HEADS, h = bh - b * H_HEADS;

    const __half* qbase = qkvh + (size_t)b * N_TOK * (3 * C_DIM) + h * D_HEAD;

    const uint32_t qa_lane = (uint32_t)((wr * 32 + (j8 & 1) * 8 + i8) * 272 + (j8 >> 1) * 16);
    const uint32_t kb_lane = (uint32_t)((wc * 64 + (j8 & 1) * 8 + i8) * 272 + (j8 >> 1) * 16);
    const uint32_t vb_lane = (uint32_t)(((wc * 64 + (j8 & 1) * 8 + i8) * 272) + ((j8 >> 1) * 8) * 2);

    // ---- load Q tile (once) ----
    #pragma unroll
    for (int i = 0; i < 8; i++) {
        int id = tid + i * 256;
        int r = id >> 4, c = id & 15;
        int q = qt * 128 + r;
        const __half* src = qbase; int bytes = 0;
        if (q < N_TOK) { src = qbase + (size_t)q * (3 * C_DIM) + c * 8; bytes = 16; }
        cp16(smb + (uint32_t)(r * 272 + c * 16), src, bytes);
    }

    // ---- compact KV load state: chunk i = base + i*16 rows ----
    const int kvr0 = tid >> 4;        // 0..15
    const int kvc = tid & 15;
    const __half* ksrc0 = qbase + (size_t)kvr0 * (3 * C_DIM) + C_DIM + kvc * 8;
    const uint32_t kvdst0 = (uint32_t)(kvr0 * 272 + kvc * 16);
    const size_t kv16 = (size_t)16 * (3 * C_DIM);
    const size_t kvstep = (size_t)128 * (3 * C_DIM);

    auto load_kv = [&](int t, int s) {
        uint32_t kb = smb + FAH_QB + (uint32_t)s * 2 * FAH_KVB;
        uint32_t vb = kb + FAH_KVB;
        const __half* kp = ksrc0 + (size_t)t * kvstep;
        int rbase = t * 128 + kvr0;
        #pragma unroll
        for (int i = 0; i < 8; i++) {
            int bytes = (rbase + 16 * i < N_TOK) ? 16 : 0;
            cp16(kb + kvdst0 + (uint32_t)(i * 16 * 272), kp + (size_t)i * kv16, bytes);
            cp16(vb + kvdst0 + (uint32_t)(i * 16 * 272), kp + C_DIM + (size_t)i * kv16, bytes);
        }
    };
    load_kv(0, 0);
    cp_commit();

    float o[2][16][4];
    #pragma unroll
    for (int mi = 0; mi < 2; mi++)
        #pragma unroll
        for (int ni = 0; ni < 16; ni++)
            #pragma unroll
            for (int r = 0; r < 4; r++) o[mi][ni][r] = 0.f;
    float mrow[4] = {-1e30f, -1e30f, -1e30f, -1e30f};
    float lrow[4] = {0.f, 0.f, 0.f, 0.f};

    for (int t = 0; t < FA_T; t++) {
        int s = t & 1;
        cp_wait<0>();
        __syncthreads();
        if (t + 1 < FA_T) load_kv(t + 1, s ^ 1);
        cp_commit();

        uint32_t kb = smb + FAH_QB + (uint32_t)s * 2 * FAH_KVB;
        uint32_t vb = kb + FAH_KVB;

        // ---- S = Q K^T (warp: 32 q x 64 kv, k=128 -> 8 k16 steps) ----
        float sa[2][8][4];
        #pragma unroll
        for (int mi = 0; mi < 2; mi++)
            #pragma unroll
            for (int ni = 0; ni < 8; ni++)
                #pragma unroll
                for (int r = 0; r < 4; r++) sa[mi][ni][r] = 0.f;

        uint32_t qb0 = smb + qa_lane;
        uint32_t kb0 = kb + kb_lane;
        #pragma unroll
        for (int ks = 0; ks < 8; ks++) {
            unsigned af[2][4];
            #pragma unroll
            for (int mi = 0; mi < 2; mi++)
                LDSM_X4(af[mi][0], af[mi][1], af[mi][2], af[mi][3],
                        qb0 + (uint32_t)(mi * 16 * 272 + ks * 32));
            #pragma unroll
            for (int g = 0; g < 4; g++) {
                unsigned kf[4];
                LDSM_X4(kf[0], kf[1], kf[2], kf[3],
                        kb0 + (uint32_t)(g * 16 * 272 + ks * 32));
                unsigned b0[2] = { kf[0], kf[2] };
                unsigned b1[2] = { kf[1], kf[3] };
                #pragma unroll
                for (int mi = 0; mi < 2; mi++) {
                    mma_f16(sa[mi][g * 2],     af[mi], b0);
                    mma_f16(sa[mi][g * 2 + 1], af[mi], b1);
                }
            }
        }

        // ---- mask (Q pre-scaled) ----
        if (t == FA_T - 1) {
            #pragma unroll
            for (int ni = 0; ni < 8; ni++) {
                int col = t * 128 + wc * 64 + ni * 8 + 2 * lc;
                if (col >= N_TOK) {
                    #pragma unroll
                    for (int mi = 0; mi < 2; mi++) { sa[mi][ni][0] = -1e30f; sa[mi][ni][2] = -1e30f; }
                }
                if (col + 1 >= N_TOK) {
                    #pragma unroll
                    for (int mi = 0; mi < 2; mi++) { sa[mi][ni][1] = -1e30f; sa[mi][ni][3] = -1e30f; }
                }
            }
        }

        // ---- online softmax (warp-local row stats) ----
        float tm[4] = {-1e30f, -1e30f, -1e30f, -1e30f};
        #pragma unroll
        for (int mi = 0; mi < 2; mi++)
            #pragma unroll
            for (int ni = 0; ni < 8; ni++) {
                tm[mi * 2 + 0] = fmaxf(tm[mi * 2 + 0], fmaxf(sa[mi][ni][0], sa[mi][ni][1]));
                tm[mi * 2 + 1] = fmaxf(tm[mi * 2 + 1], fmaxf(sa[mi][ni][2], sa[mi][ni][3]));
            }
        #pragma unroll
        for (int j = 0; j < 4; j++) {
            tm[j] = fmaxf(tm[j], __shfl_xor_sync(0xffffffffu, tm[j], 1));
            tm[j] = fmaxf(tm[j], __shfl_xor_sync(0xffffffffu, tm[j], 2));
        }
        float fj[4];
        #pragma unroll
        for (int j = 0; j < 4; j++) {
            float mn = fmaxf(mrow[j], tm[j]);
            fj[j] = __expf(mrow[j] - mn);
            mrow[j] = mn;
        }
        float rs[4] = {0.f, 0.f, 0.f, 0.f};
        #pragma unroll
        for (int mi = 0; mi < 2; mi++)
            #pragma unroll
            for (int ni = 0; ni < 8; ni++) {
                sa[mi][ni][0] = __expf(sa[mi][ni][0] - mrow[mi * 2]);     rs[mi * 2] += sa[mi][ni][0];
                sa[mi][ni][1] = __expf(sa[mi][ni][1] - mrow[mi * 2]);     rs[mi * 2] += sa[mi][ni][1];
                sa[mi][ni][2] = __expf(sa[mi][ni][2] - mrow[mi * 2 + 1]); rs[mi * 2 + 1] += sa[mi][ni][2];
                sa[mi][ni][3] = __expf(sa[mi][ni][3] - mrow[mi * 2 + 1]); rs[mi * 2 + 1] += sa[mi][ni][3];
            }
        #pragma unroll
        for (int j = 0; j < 4; j++) {
            rs[j] += __shfl_xor_sync(0xffffffffu, rs[j], 1);
            rs[j] += __shfl_xor_sync(0xffffffffu, rs[j], 2);
            lrow[j] = lrow[j] * fj[j] + rs[j];
        }
        #pragma unroll
        for (int mi = 0; mi < 2; mi++)
            #pragma unroll
            for (int ni = 0; ni < 16; ni++) {
                o[mi][ni][0] *= fj[mi * 2];     o[mi][ni][1] *= fj[mi * 2];
                o[mi][ni][2] *= fj[mi * 2 + 1]; o[mi][ni][3] *= fj[mi * 2 + 1];
            }

        // ---- O += P V  (k = 128 own kv -> 4 k16 steps) ----
        uint32_t vb0 = vb + vb_lane;
        #pragma unroll
        for (int ks2 = 0; ks2 < 4; ks2++) {
            unsigned a[2][4];
            #pragma unroll
            for (int mi = 0; mi < 2; mi++) {
                a[mi][0] = pack_h2(sa[mi][2 * ks2][0],     sa[mi][2 * ks2][1]);
                a[mi][1] = pack_h2(sa[mi][2 * ks2][2],     sa[mi][2 * ks2][3]);
                a[mi][2] = pack_h2(sa[mi][2 * ks2 + 1][0], sa[mi][2 * ks2 + 1][1]);
                a[mi][3] = pack_h2(sa[mi][2 * ks2 + 1][2], sa[mi][2 * ks2 + 1][3]);
            }
            #pragma unroll
            for (int nb = 0; nb < 8; nb++) {
                unsigned vf[4];
                LDSM_X4_T(vf[0], vf[1], vf[2], vf[3],
                          vb0 + (uint32_t)(ks2 * 16 * 272 + nb * 32));
                unsigned b0[2] = { vf[0], vf[1] };
                unsigned b1[2] = { vf[2], vf[3] };
                #pragma unroll
                for (int mi = 0; mi < 2; mi++) {
                    mma_f16(o[mi][nb * 2],     a[mi], b0);
                    mma_f16(o[mi][nb * 2 + 1], a[mi], b1);
                }
            }
        }
    }

    // ---- split-KV merge via float buffer aliasing KV region ----
    float* Ms = reinterpret_cast<float*>(fsm + FAH_QB);              // [128][132] floats
    float* stats = reinterpret_cast<float*>(fsm + FAH_QB + 128 * 132 * 4);  // [128][2]
    __syncthreads();
    if (wc == 1) {
        #pragma unroll
        for (int mi = 0; mi < 2; mi++) {
            int r0 = wr * 32 + mi * 16 + lr;
            #pragma unroll
            for (int ni = 0; ni < 16; ni++) {
                *reinterpret_cast<float2*>(&Ms[r0 * 132 + ni * 8 + 2 * lc]) =
                    make_float2(o[mi][ni][0], o[mi][ni][1]);
                *reinterpret_cast<float2*>(&Ms[(r0 + 8) * 132 + ni * 8 + 2 * lc]) =
                    make_float2(o[mi][ni][2], o[mi][ni][3]);
            }
            if (lc == 0) {
                stats[r0 * 2]           = mrow[mi * 2];
                stats[r0 * 2 + 1]       = lrow[mi * 2];
                stats[(r0 + 8) * 2]     = mrow[mi * 2 + 1];
                stats[(r0 + 8) * 2 + 1] = lrow[mi * 2 + 1];
            }
        }
    }
    __syncthreads();
    if (wc == 0) {
        #pragma unroll
        for (int mi = 0; mi < 2; mi++) {
            #pragma unroll
            for (int half = 0; half < 2; half++) {
                int r0 = wr * 32 + mi * 16 + lr + half * 8;
                int j = mi * 2 + half;
                float m1 = stats[r0 * 2];
                float l1 = stats[r0 * 2 + 1];
                float mm = fmaxf(mrow[j], m1);
                float f0 = __expf(mrow[j] - mm), f1 = __expf(m1 - mm);
                float ll = lrow[j] * f0 + l1 * f1;
                float inv = 1.f / ll;
                int rg = qt * 128 + r0;
                if (rg < N_TOK) {
                    __half* dst = Og + ((size_t)(b * N_TOK + rg)) * C_DIM + h * D_HEAD;
                    #pragma unroll
                    for (int ni = 0; ni < 16; ni++) {
                        float2 o1 = *reinterpret_cast<float2*>(&Ms[r0 * 132 + ni * 8 + 2 * lc]);
                        float v0 = (o[mi][ni][half * 2]     * f0 + o1.x * f1) * inv;
                        float v1 = (o[mi][ni][half * 2 + 1] * f0 + o1.y * f1) * inv;
                        *reinterpret_cast<__half2*>(&dst[ni * 8 + 2 * lc]) =
                            __floats2half2_rn(v0, v1);
                    }
                }
            }
        }
    }
}

// ===================== pre-processing kernels =====================

__global__ void conv_half(const float* __restrict__ in, __half* __restrict__ out, long n4)
{
    long i = (long)blockIdx.x * blockDim.x + threadIdx.x;
    long stride = (long)gridDim.x * blockDim.x;
    for (; i < n4; i += stride) {
        float4 v = reinterpret_cast<const float4*>(in)[i];
        reinterpret_cast<__half2*>(out)[i * 2]     = __floats2half2_rn(v.x, v.y);
        reinterpret_cast<__half2*>(out)[i * 2 + 1] = __floats2half2_rn(v.z, v.w);
    }
}

// RMSNorm q,k over full C, fp16 in/out in place; q pre-scaled by 1/sqrt(D).
__global__ void rmsnorm_qk_h(__half* __restrict__ qkvh,
                             const float* __restrict__ qw, const float* __restrict__ kw)
{
    __half* row = qkvh + (size_t)blockIdx.x * (3 * C_DIM);
    int tid = threadIdx.x;
    const float scale = 0.088388347648318447f;   // 1/sqrt(128)
    float sq = 0.f, sk = 0.f;
    for (int i = tid * 8; i < C_DIM; i += 256 * 8) {
        float4 qr = *reinterpret_cast<const float4*>(row + i);           // 8 halfs
        float4 kr = *reinterpret_cast<const float4*>(row + C_DIM + i);
        const __half2* qh = reinterpret_cast<const __half2*>(&qr);
        const __half2* kh = reinterpret_cast<const __half2*>(&kr);
        #pragma unroll
        for (int j = 0; j < 4; j++) {
            float2 q2 = __half22float2(qh[j]);
            float2 k2 = __half22float2(kh[j]);
            sq += q2.x * q2.x + q2.y * q2.y;
            sk += k2.x * k2.x + k2.y * k2.y;
        }
    }
    #pragma unroll
    for (int o = 16; o; o >>= 1) {
        sq += __shfl_xor_sync(0xffffffffu, sq, o);
        sk += __shfl_xor_sync(0xffffffffu, sk, o);
    }
    __shared__ float s1[8], s2[8];
    int lane = tid & 31, warp = tid >> 5;
    if (lane == 0) { s1[warp] = sq; s2[warp] = sk; }
    __syncthreads();
    if (tid == 0) {
        float a = 0.f, b = 0.f;
        #pragma unroll
        for (int w = 0; w < 8; w++) { a += s1[w]; b += s2[w]; }
        s1[0] = rsqrtf(a / C_DIM + 1e-6f);
        s2[0] = rsqrtf(b / C_DIM + 1e-6f);
    }
    __syncthreads();
    float invq = s1[0] * scale, invk = s2[0];
    for (int i = tid * 8; i < C_DIM; i += 256 * 8) {
        float4 qr = *reinterpret_cast<const float4*>(row + i);
        float4 kr = *reinterpret_cast<const float4*>(row + C_DIM + i);
        __half2* qh = reinterpret_cast<__half2*>(&qr);
        __half2* kh = reinterpret_cast<__half2*>(&kr);
        float4 qo, ko;
        __half2* qoh = reinterpret_cast<__half2*>(&qo);
        __half2* koh = reinterpret_cast<__half2*>(&ko);
        #pragma unroll
        for (int j = 0; j < 4; j++) {
            float2 q2 = __half22float2(qh[j]);
            float2 k2 = __half22float2(kh[j]);
            qoh[j] = __floats2half2_rn(q2.x * invq * qw[i + j * 2], q2.y * invq * qw[i + j * 2 + 1]);
            koh[j] = __floats2half2_rn(k2.x * invk * kw[i + j * 2], k2.y * invk * kw[i + j * 2 + 1]);
        }
        *reinterpret_cast<float4*>(row + i) = qo;
        *reinterpret_cast<float4*>(row + C_DIM + i) = ko;
    }
}

extern "C" void kernel_launch(void* const* d_in, const int* in_sizes, int n_in,
                              void* d_out, int out_size)
{
    const float* x        = (const float*)d_in[0];
    const float* qkv_w    = (const float*)d_in[1];
    const float* qkv_b    = (const float*)d_in[2];
    const float* q_norm_w = (const float*)d_in[3];
    const float* k_norm_w = (const float*)d_in[4];
    const float* proj_w   = (const float*)d_in[5];
    const float* proj_b   = (const float*)d_in[6];
    float* out = (float*)d_out;

    __half *qkvh, *xh, *wqkvh, *wprojh, *atth;
    cudaGetSymbolAddress((void**)&qkvh,   g_qkvh);
    cudaGetSymbolAddress((void**)&xh,     g_xh);
    cudaGetSymbolAddress((void**)&wqkvh,  g_wqkvh);
    cudaGetSymbolAddress((void**)&wprojh, g_wprojh);
    cudaGetSymbolAddress((void**)&atth,   g_atth);

    cudaFuncSetAttribute(hgemm<__half>, cudaFuncAttributeMaxDynamicSharedMemorySize, HG_SMEM);
    cudaFuncSetAttribute(hgemm<float>,  cudaFuncAttributeMaxDynamicSharedMemorySize, HG_SMEM);
    cudaFuncSetAttribute(flash_attn_h, cudaFuncAttributeMaxDynamicSharedMemorySize, FAH_SMEM);

    dim3 blk(256);

    // 0. Convert GEMM operands to fp16
    conv_half<<<2048, 256>>>(x, xh, (long)M_ROWS * C_DIM / 4);
    conv_half<<<2048, 256>>>(qkv_w, wqkvh, (long)C_DIM * 3 * C_DIM / 4);
    conv_half<<<2048, 256>>>(proj_w, wprojh, (long)C_DIM * C_DIM / 4);

    // 1. QKV GEMM (fp16 in, fp16 out): [8200,3200] x [3200,9600] + bias
    {
        int TM = (M_ROWS + 127) / 128;          // 65
        int TN = (3 * C_DIM) / 128;             // 75
        hgemm<__half><<<dim3(TM * TN, 1, 1), blk, HG_SMEM>>>(
            xh, wqkvh, qkv_b, qkvh, M_ROWS, 3 * C_DIM, C_DIM,
            C_DIM, 3 * C_DIM, 3 * C_DIM, TM, TN);
    }

    // 2. RMSNorm q,k in place on fp16 (q pre-scaled)
    rmsnorm_qk_h<<<M_ROWS, blk>>>(qkvh, q_norm_w, k_norm_w);

    // 3-5. Fused flash attention (fp16, KV tile 128) -> g_atth
    flash_attn_h<<<dim3(9, 200), blk, FAH_SMEM>>>(qkvh, atth);

    // 6. Proj GEMM (fp16 in, f32 out): [8200,3200] x [3200,3200] + bias -> out
    {
        int TM = (M_ROWS + 127) / 128;          // 65
        int TN = C_DIM / 128;                   // 25
        hgemm<float><<<dim3(TM * TN, 1, 1), blk, HG_SMEM>>>(
            atth, wprojh, proj_b, out, M_ROWS, C_DIM, C_DIM,
            C_DIM, C_DIM, C_DIM, TM, TN);
    }
}